// round 1
// baseline (speedup 1.0000x reference)
#include <cuda_runtime.h>

// out[B,18] = Theta(x)[B,1330] @ (big_xi * mask)[1330,18]
// x = concat(z[B,16], betas[B,2]); Theta = all monomials of degree 0..3,
// combinations_with_replacement order == nested i<=j<=k loops.

#define BLOCK   256
#define NVARS   18
#define P_TOT   1330
#define WPAD    20      // padded W row stride (floats) -> 80B, 16B aligned rows
#define NACC    9       // 18 outputs as 9 packed f32x2 accumulators

__device__ __forceinline__ unsigned long long pack2(float t) {
    unsigned long long r;
    asm("mov.b64 %0, {%1, %1};" : "=l"(r) : "f"(t));
    return r;
}
__device__ __forceinline__ unsigned long long ffma2(unsigned long long a,
                                                    unsigned long long b,
                                                    unsigned long long c) {
    unsigned long long r;
    asm("fma.rn.f32x2 %0, %1, %2, %3;" : "=l"(r) : "l"(a), "l"(b), "l"(c));
    return r;
}
__device__ __forceinline__ void unpack2(unsigned long long v, float& x, float& y) {
    asm("mov.b64 {%0, %1}, %2;" : "=f"(x), "=f"(y) : "l"(v));
}

// 9 packed FMAs against one W row (w16-aligned, 20-float stride).
#define ACC9(T2, WROW) do {                                                   \
    const ulonglong2* _wv = (const ulonglong2*)(WROW);                        \
    ulonglong2 _w01 = _wv[0], _w23 = _wv[1], _w45 = _wv[2], _w67 = _wv[3];    \
    unsigned long long _w8 = *(const unsigned long long*)((WROW) + 16);       \
    acc[0] = ffma2(T2, _w01.x, acc[0]);                                       \
    acc[1] = ffma2(T2, _w01.y, acc[1]);                                       \
    acc[2] = ffma2(T2, _w23.x, acc[2]);                                       \
    acc[3] = ffma2(T2, _w23.y, acc[3]);                                       \
    acc[4] = ffma2(T2, _w45.x, acc[4]);                                       \
    acc[5] = ffma2(T2, _w45.y, acc[5]);                                       \
    acc[6] = ffma2(T2, _w67.x, acc[6]);                                       \
    acc[7] = ffma2(T2, _w67.y, acc[7]);                                       \
    acc[8] = ffma2(T2, _w8,    acc[8]);                                       \
} while (0)

__global__ __launch_bounds__(BLOCK)
void vindy_poly_kernel(const float* __restrict__ z,
                       const float* __restrict__ betas,
                       const float* __restrict__ big_xi,
                       const float* __restrict__ mask,
                       float* __restrict__ out,
                       int rows)
{
    extern __shared__ __align__(16) float smem[];
    float* Wsh = smem;                       // P_TOT * WPAD floats (padded rows)
    float* xsh = smem + P_TOT * WPAD;        // NVARS * BLOCK floats (transposed)

    const int tid = threadIdx.x;
    const int row = blockIdx.x * BLOCK + tid;

    // Stage W = big_xi * mask into shared, rows padded to WPAD floats.
    for (int idx = tid; idx < P_TOT * NVARS; idx += BLOCK) {
        int p = idx / NVARS;
        int n = idx - p * NVARS;
        Wsh[p * WPAD + n] = big_xi[idx] * mask[idx];
    }

    // Stage x = [z | betas] transposed: xsh[v*BLOCK + tid] (conflict-free LDS).
    if (row < rows) {
        const float4* zr = (const float4*)(z + (size_t)row * 16);
        float4 a = zr[0], b = zr[1], c = zr[2], d = zr[3];
        xsh[ 0 * BLOCK + tid] = a.x;  xsh[ 1 * BLOCK + tid] = a.y;
        xsh[ 2 * BLOCK + tid] = a.z;  xsh[ 3 * BLOCK + tid] = a.w;
        xsh[ 4 * BLOCK + tid] = b.x;  xsh[ 5 * BLOCK + tid] = b.y;
        xsh[ 6 * BLOCK + tid] = b.z;  xsh[ 7 * BLOCK + tid] = b.w;
        xsh[ 8 * BLOCK + tid] = c.x;  xsh[ 9 * BLOCK + tid] = c.y;
        xsh[10 * BLOCK + tid] = c.z;  xsh[11 * BLOCK + tid] = c.w;
        xsh[12 * BLOCK + tid] = d.x;  xsh[13 * BLOCK + tid] = d.y;
        xsh[14 * BLOCK + tid] = d.z;  xsh[15 * BLOCK + tid] = d.w;
        const float2 bb = *(const float2*)(betas + (size_t)row * 2);
        xsh[16 * BLOCK + tid] = bb.x; xsh[17 * BLOCK + tid] = bb.y;
    }
    __syncthreads();

    if (row >= rows) return;

    unsigned long long acc[NACC];
    const float* w = Wsh;

    // Degree 0: constant column contributes W row 0 directly.
    {
        const ulonglong2* wv = (const ulonglong2*)w;
        ulonglong2 w01 = wv[0], w23 = wv[1], w45 = wv[2], w67 = wv[3];
        acc[0] = w01.x; acc[1] = w01.y;
        acc[2] = w23.x; acc[3] = w23.y;
        acc[4] = w45.x; acc[5] = w45.y;
        acc[6] = w67.x; acc[7] = w67.y;
        acc[8] = *(const unsigned long long*)(w + 16);
        w += WPAD;
    }

    const float* xcol = xsh + tid;

    // Degree 1
    #pragma unroll 1
    for (int i = 0; i < NVARS; ++i) {
        float xi = xcol[i * BLOCK];
        unsigned long long t2 = pack2(xi);
        ACC9(t2, w);
        w += WPAD;
    }

    // Degree 2
    #pragma unroll 1
    for (int i = 0; i < NVARS; ++i) {
        float xi = xcol[i * BLOCK];
        #pragma unroll 1
        for (int j = i; j < NVARS; ++j) {
            float xj = xcol[j * BLOCK];
            unsigned long long t2 = pack2(xi * xj);
            ACC9(t2, w);
            w += WPAD;
        }
    }

    // Degree 3 (prefix reuse: pij = xi*xj hoisted out of the k loop)
    #pragma unroll 1
    for (int i = 0; i < NVARS; ++i) {
        float xi = xcol[i * BLOCK];
        #pragma unroll 1
        for (int j = i; j < NVARS; ++j) {
            float pij = xi * xcol[j * BLOCK];
            #pragma unroll 4
            for (int k = j; k < NVARS; ++k) {
                float xk = xcol[k * BLOCK];
                unsigned long long t2 = pack2(pij * xk);
                ACC9(t2, w);
                w += WPAD;
            }
        }
    }

    // Write 18 outputs as 9 float2 stores (8B aligned: row*72 + n*8).
    float* o = out + (size_t)row * NVARS;
    #pragma unroll
    for (int n = 0; n < NACC; ++n) {
        float a, b;
        unpack2(acc[n], a, b);
        ((float2*)o)[n] = make_float2(a, b);
    }
}

extern "C" void kernel_launch(void* const* d_in, const int* in_sizes, int n_in,
                              void* d_out, int out_size)
{
    const float* z      = (const float*)d_in[0];
    const float* betas  = (const float*)d_in[1];
    const float* big_xi = (const float*)d_in[2];
    const float* mask   = (const float*)d_in[3];
    float* out = (float*)d_out;

    const int rows = in_sizes[0] / 16;   // z is [rows, 16]
    const int smem_bytes = (P_TOT * WPAD + NVARS * BLOCK) * (int)sizeof(float);

    cudaFuncSetAttribute(vindy_poly_kernel,
                         cudaFuncAttributeMaxDynamicSharedMemorySize, smem_bytes);

    const int grid = (rows + BLOCK - 1) / BLOCK;
    vindy_poly_kernel<<<grid, BLOCK, smem_bytes>>>(z, betas, big_xi, mask, out, rows);
}

// round 2
// speedup vs baseline: 1.2214x; 1.2214x over previous
#include <cuda_runtime.h>

// out[B,18] = Theta(x)[B,1330] @ (big_xi * mask)[1330,18]
// x = concat(z[B,16], betas[B,2]); Theta = monomials deg 0..3 in
// combinations_with_replacement order == nested i<=j<=k loops.
//
// R=2 rows per thread: the broadcast W row loads from shared are amortized
// over two rows of FFMA2 work, halving shared-crossbar phases per FLOP.

#define BLOCK   224     // 7 warps
#define R_ROWS  2
#define CHUNK   (BLOCK * R_ROWS)   // 448 rows per block
#define NVARS   18
#define P_TOT   1330
#define WPAD    20      // padded W row stride (floats): 80B, 16B-aligned rows
#define NACC    9       // 18 outputs as 9 packed f32x2 accumulators

__device__ __forceinline__ unsigned long long pack2(float t) {
    unsigned long long r;
    asm("mov.b64 %0, {%1, %1};" : "=l"(r) : "f"(t));
    return r;
}
__device__ __forceinline__ unsigned long long ffma2(unsigned long long a,
                                                    unsigned long long b,
                                                    unsigned long long c) {
    unsigned long long r;
    asm("fma.rn.f32x2 %0, %1, %2, %3;" : "=l"(r) : "l"(a), "l"(b), "l"(c));
    return r;
}
__device__ __forceinline__ void unpack2(unsigned long long v, float& x, float& y) {
    asm("mov.b64 {%0, %1}, %2;" : "=f"(x), "=f"(y) : "l"(v));
}

// Load one padded W row (5 LDS, broadcast) and apply to both rows' accumulators.
#define ACC2ROWS(T2A, T2B, WROW) do {                                         \
    const ulonglong2* _wv = (const ulonglong2*)(WROW);                        \
    ulonglong2 _w01 = _wv[0], _w23 = _wv[1], _w45 = _wv[2], _w67 = _wv[3];    \
    unsigned long long _w8 = *(const unsigned long long*)((WROW) + 16);       \
    accA[0] = ffma2(T2A, _w01.x, accA[0]);  accB[0] = ffma2(T2B, _w01.x, accB[0]); \
    accA[1] = ffma2(T2A, _w01.y, accA[1]);  accB[1] = ffma2(T2B, _w01.y, accB[1]); \
    accA[2] = ffma2(T2A, _w23.x, accA[2]);  accB[2] = ffma2(T2B, _w23.x, accB[2]); \
    accA[3] = ffma2(T2A, _w23.y, accA[3]);  accB[3] = ffma2(T2B, _w23.y, accB[3]); \
    accA[4] = ffma2(T2A, _w45.x, accA[4]);  accB[4] = ffma2(T2B, _w45.x, accB[4]); \
    accA[5] = ffma2(T2A, _w45.y, accA[5]);  accB[5] = ffma2(T2B, _w45.y, accB[5]); \
    accA[6] = ffma2(T2A, _w67.x, accA[6]);  accB[6] = ffma2(T2B, _w67.x, accB[6]); \
    accA[7] = ffma2(T2A, _w67.y, accA[7]);  accB[7] = ffma2(T2B, _w67.y, accB[7]); \
    accA[8] = ffma2(T2A, _w8,    accA[8]);  accB[8] = ffma2(T2B, _w8,    accB[8]); \
} while (0)

__global__ __launch_bounds__(BLOCK)
void vindy_poly_kernel(const float* __restrict__ z,
                       const float* __restrict__ betas,
                       const float* __restrict__ big_xi,
                       const float* __restrict__ mask,
                       float* __restrict__ out,
                       int rows)
{
    extern __shared__ __align__(16) float smem[];
    float* Wsh = smem;                       // P_TOT * WPAD floats (padded rows)
    float* xsh = smem + P_TOT * WPAD;        // NVARS * CHUNK floats (transposed)

    const int tid  = threadIdx.x;
    const int base = blockIdx.x * CHUNK;

    // Stage W = big_xi * mask into shared (padded rows).
    for (int p = tid; p < P_TOT; p += BLOCK) {
        const float* gx = big_xi + p * NVARS;
        const float* gm = mask   + p * NVARS;
        float* wrow = Wsh + p * WPAD;
        #pragma unroll
        for (int n = 0; n < NVARS; ++n) wrow[n] = gx[n] * gm[n];
    }

    // Stage this block's x = [z | betas] transposed: xsh[v*CHUNK + r].
    #pragma unroll
    for (int rr = 0; rr < R_ROWS; ++rr) {
        const int rloc = tid + rr * BLOCK;
        int grow = base + rloc;
        if (grow > rows - 1) grow = rows - 1;     // clamp (results discarded)
        const float4* zr = (const float4*)(z + (size_t)grow * 16);
        float4 a = zr[0], b = zr[1], c = zr[2], d = zr[3];
        xsh[ 0 * CHUNK + rloc] = a.x;  xsh[ 1 * CHUNK + rloc] = a.y;
        xsh[ 2 * CHUNK + rloc] = a.z;  xsh[ 3 * CHUNK + rloc] = a.w;
        xsh[ 4 * CHUNK + rloc] = b.x;  xsh[ 5 * CHUNK + rloc] = b.y;
        xsh[ 6 * CHUNK + rloc] = b.z;  xsh[ 7 * CHUNK + rloc] = b.w;
        xsh[ 8 * CHUNK + rloc] = c.x;  xsh[ 9 * CHUNK + rloc] = c.y;
        xsh[10 * CHUNK + rloc] = c.z;  xsh[11 * CHUNK + rloc] = c.w;
        xsh[12 * CHUNK + rloc] = d.x;  xsh[13 * CHUNK + rloc] = d.y;
        xsh[14 * CHUNK + rloc] = d.z;  xsh[15 * CHUNK + rloc] = d.w;
        const float2 bb = *(const float2*)(betas + (size_t)grow * 2);
        xsh[16 * CHUNK + rloc] = bb.x; xsh[17 * CHUNK + rloc] = bb.y;
    }
    __syncthreads();

    unsigned long long accA[NACC], accB[NACC];
    const float* w = Wsh;

    // Degree 0: constant column contributes W row 0 directly.
    {
        const ulonglong2* wv = (const ulonglong2*)w;
        ulonglong2 w01 = wv[0], w23 = wv[1], w45 = wv[2], w67 = wv[3];
        unsigned long long w8 = *(const unsigned long long*)(w + 16);
        accA[0] = w01.x; accA[1] = w01.y; accA[2] = w23.x; accA[3] = w23.y;
        accA[4] = w45.x; accA[5] = w45.y; accA[6] = w67.x; accA[7] = w67.y;
        accA[8] = w8;
        #pragma unroll
        for (int n = 0; n < NACC; ++n) accB[n] = accA[n];
        w += WPAD;
    }

    const float* xA = xsh + tid;
    const float* xB = xsh + tid + BLOCK;

    // Degree 1
    #pragma unroll 1
    for (int i = 0; i < NVARS; ++i) {
        unsigned long long tA = pack2(xA[i * CHUNK]);
        unsigned long long tB = pack2(xB[i * CHUNK]);
        ACC2ROWS(tA, tB, w);
        w += WPAD;
    }

    // Degree 2
    #pragma unroll 1
    for (int i = 0; i < NVARS; ++i) {
        float xiA = xA[i * CHUNK];
        float xiB = xB[i * CHUNK];
        #pragma unroll 2
        for (int j = i; j < NVARS; ++j) {
            unsigned long long tA = pack2(xiA * xA[j * CHUNK]);
            unsigned long long tB = pack2(xiB * xB[j * CHUNK]);
            ACC2ROWS(tA, tB, w);
            w += WPAD;
        }
    }

    // Degree 3 (pij hoisted out of the k loop)
    #pragma unroll 1
    for (int i = 0; i < NVARS; ++i) {
        float xiA = xA[i * CHUNK];
        float xiB = xB[i * CHUNK];
        #pragma unroll 1
        for (int j = i; j < NVARS; ++j) {
            float pijA = xiA * xA[j * CHUNK];
            float pijB = xiB * xB[j * CHUNK];
            #pragma unroll 2
            for (int k = j; k < NVARS; ++k) {
                unsigned long long tA = pack2(pijA * xA[k * CHUNK]);
                unsigned long long tB = pack2(pijB * xB[k * CHUNK]);
                ACC2ROWS(tA, tB, w);
                w += WPAD;
            }
        }
    }

    // Write 18 outputs per row as 9 float2 stores (rows are 72B strided).
    #pragma unroll
    for (int rr = 0; rr < R_ROWS; ++rr) {
        const int grow = base + tid + rr * BLOCK;
        if (grow < rows) {
            unsigned long long* acc = (rr == 0) ? accA : accB;
            float* o = out + (size_t)grow * NVARS;
            #pragma unroll
            for (int n = 0; n < NACC; ++n) {
                float a, b;
                unpack2(acc[n], a, b);
                ((float2*)o)[n] = make_float2(a, b);
            }
        }
    }
}

extern "C" void kernel_launch(void* const* d_in, const int* in_sizes, int n_in,
                              void* d_out, int out_size)
{
    const float* z      = (const float*)d_in[0];
    const float* betas  = (const float*)d_in[1];
    const float* big_xi = (const float*)d_in[2];
    const float* mask   = (const float*)d_in[3];
    float* out = (float*)d_out;

    const int rows = in_sizes[0] / 16;   // z is [rows, 16]
    const int smem_bytes = (P_TOT * WPAD + NVARS * CHUNK) * (int)sizeof(float);

    cudaFuncSetAttribute(vindy_poly_kernel,
                         cudaFuncAttributeMaxDynamicSharedMemorySize, smem_bytes);

    const int grid = (rows + CHUNK - 1) / CHUNK;
    vindy_poly_kernel<<<grid, BLOCK, smem_bytes>>>(z, betas, big_xi, mask, out, rows);
}

// round 4
// speedup vs baseline: 1.5337x; 1.2557x over previous
#include <cuda_runtime.h>

// out[B,18] = Theta(x)[B,1330] @ (big_xi * mask)[1330,18]
// x = concat(z[B,16], betas[B,2]); Theta = monomials deg 0..3 in
// combinations_with_replacement order == nested i<=j<=k loops.
//
// R=4 rows per thread: each broadcast W-row load (5 LDS) feeds 36 independent
// FFMA2 -> ILP hides LDS latency at 1 CTA/SM; grid=147 ~ one balanced wave.

#define BLOCK   224     // 7 warps
#define R_ROWS  4
#define CHUNK   (BLOCK * R_ROWS)   // 896 rows per block
#define NVARS   18
#define P_TOT   1330
#define WPAD    20      // padded W row stride (floats): 80B, 16B-aligned rows
#define NACC    9       // 18 outputs as 9 packed f32x2 accumulators

typedef unsigned long long u64;

__device__ __forceinline__ u64 pack2(float t) {
    u64 r;
    asm("mov.b64 %0, {%1, %1};" : "=l"(r) : "f"(t));
    return r;
}
__device__ __forceinline__ u64 ffma2(u64 a, u64 b, u64 c) {
    u64 r;
    asm("fma.rn.f32x2 %0, %1, %2, %3;" : "=l"(r) : "l"(a), "l"(b), "l"(c));
    return r;
}
__device__ __forceinline__ void unpack2(u64 v, float& x, float& y) {
    asm("mov.b64 {%0, %1}, %2;" : "=f"(x), "=f"(y) : "l"(v));
}

__global__ __launch_bounds__(BLOCK, 1)
void vindy_poly_kernel(const float* __restrict__ z,
                       const float* __restrict__ betas,
                       const float* __restrict__ big_xi,
                       const float* __restrict__ mask,
                       float* __restrict__ out,
                       int rows)
{
    extern __shared__ __align__(16) float smem[];
    float* Wsh = smem;                       // P_TOT * WPAD floats (padded rows)
    float* xsh = smem + P_TOT * WPAD;        // NVARS * CHUNK floats (transposed)

    const int tid  = threadIdx.x;
    const int base = blockIdx.x * CHUNK;

    // Stage W = big_xi * mask into shared (padded rows).
    for (int p = tid; p < P_TOT; p += BLOCK) {
        const float* gx = big_xi + p * NVARS;
        const float* gm = mask   + p * NVARS;
        float* wrow = Wsh + p * WPAD;
        #pragma unroll
        for (int n = 0; n < NVARS; ++n) wrow[n] = gx[n] * gm[n];
    }

    // Stage this block's x = [z | betas] transposed: xsh[v*CHUNK + r].
    #pragma unroll
    for (int rr = 0; rr < R_ROWS; ++rr) {
        const int rloc = tid + rr * BLOCK;
        int grow = base + rloc;
        if (grow > rows - 1) grow = rows - 1;     // clamp (extra results discarded)
        const float4* zr = (const float4*)(z + (size_t)grow * 16);
        float4 a = zr[0], b = zr[1], c = zr[2], d = zr[3];
        xsh[ 0 * CHUNK + rloc] = a.x;  xsh[ 1 * CHUNK + rloc] = a.y;
        xsh[ 2 * CHUNK + rloc] = a.z;  xsh[ 3 * CHUNK + rloc] = a.w;
        xsh[ 4 * CHUNK + rloc] = b.x;  xsh[ 5 * CHUNK + rloc] = b.y;
        xsh[ 6 * CHUNK + rloc] = b.z;  xsh[ 7 * CHUNK + rloc] = b.w;
        xsh[ 8 * CHUNK + rloc] = c.x;  xsh[ 9 * CHUNK + rloc] = c.y;
        xsh[10 * CHUNK + rloc] = c.z;  xsh[11 * CHUNK + rloc] = c.w;
        xsh[12 * CHUNK + rloc] = d.x;  xsh[13 * CHUNK + rloc] = d.y;
        xsh[14 * CHUNK + rloc] = d.z;  xsh[15 * CHUNK + rloc] = d.w;
        const float2 bb = *(const float2*)(betas + (size_t)grow * 2);
        xsh[16 * CHUNK + rloc] = bb.x; xsh[17 * CHUNK + rloc] = bb.y;
    }
    __syncthreads();

    u64 acc[R_ROWS][NACC];
    const float* w = Wsh;

    // Degree 0: constant column contributes W row 0 directly.
    {
        const ulonglong2* wv = (const ulonglong2*)w;
        ulonglong2 w01 = wv[0], w23 = wv[1], w45 = wv[2], w67 = wv[3];
        u64 w8 = *(const u64*)(w + 16);
        #pragma unroll
        for (int r = 0; r < R_ROWS; ++r) {
            acc[r][0] = w01.x; acc[r][1] = w01.y;
            acc[r][2] = w23.x; acc[r][3] = w23.y;
            acc[r][4] = w45.x; acc[r][5] = w45.y;
            acc[r][6] = w67.x; acc[r][7] = w67.y;
            acc[r][8] = w8;
        }
        w += WPAD;
    }

    // Per-row x column bases (stride CHUNK floats between variables).
    const float* xb[R_ROWS];
    #pragma unroll
    for (int r = 0; r < R_ROWS; ++r) xb[r] = xsh + tid + r * BLOCK;

    // Apply one W row to all R_ROWS accumulators given packed theta t[r].
    #define ACCR(T) do {                                                      \
        const ulonglong2* _wv = (const ulonglong2*)w;                         \
        ulonglong2 _w01 = _wv[0], _w23 = _wv[1], _w45 = _wv[2], _w67 = _wv[3];\
        u64 _w8 = *(const u64*)(w + 16);                                      \
        _Pragma("unroll")                                                     \
        for (int _r = 0; _r < R_ROWS; ++_r) {                                 \
            acc[_r][0] = ffma2((T)[_r], _w01.x, acc[_r][0]);                  \
            acc[_r][1] = ffma2((T)[_r], _w01.y, acc[_r][1]);                  \
            acc[_r][2] = ffma2((T)[_r], _w23.x, acc[_r][2]);                  \
            acc[_r][3] = ffma2((T)[_r], _w23.y, acc[_r][3]);                  \
            acc[_r][4] = ffma2((T)[_r], _w45.x, acc[_r][4]);                  \
            acc[_r][5] = ffma2((T)[_r], _w45.y, acc[_r][5]);                  \
            acc[_r][6] = ffma2((T)[_r], _w67.x, acc[_r][6]);                  \
            acc[_r][7] = ffma2((T)[_r], _w67.y, acc[_r][7]);                  \
            acc[_r][8] = ffma2((T)[_r], _w8,    acc[_r][8]);                  \
        }                                                                     \
        w += WPAD;                                                            \
    } while (0)

    // Degree 1
    #pragma unroll 1
    for (int i = 0; i < NVARS; ++i) {
        u64 t[R_ROWS];
        #pragma unroll
        for (int r = 0; r < R_ROWS; ++r) t[r] = pack2(xb[r][i * CHUNK]);
        ACCR(t);
    }

    // Degree 2
    #pragma unroll 1
    for (int i = 0; i < NVARS; ++i) {
        float xi[R_ROWS];
        #pragma unroll
        for (int r = 0; r < R_ROWS; ++r) xi[r] = xb[r][i * CHUNK];
        #pragma unroll 1
        for (int j = i; j < NVARS; ++j) {
            u64 t[R_ROWS];
            #pragma unroll
            for (int r = 0; r < R_ROWS; ++r) t[r] = pack2(xi[r] * xb[r][j * CHUNK]);
            ACCR(t);
        }
    }

    // Degree 3 (pij hoisted out of the k loop)
    #pragma unroll 1
    for (int i = 0; i < NVARS; ++i) {
        float xi[R_ROWS];
        #pragma unroll
        for (int r = 0; r < R_ROWS; ++r) xi[r] = xb[r][i * CHUNK];
        #pragma unroll 1
        for (int j = i; j < NVARS; ++j) {
            float pij[R_ROWS];
            #pragma unroll
            for (int r = 0; r < R_ROWS; ++r) pij[r] = xi[r] * xb[r][j * CHUNK];
            #pragma unroll 2
            for (int k = j; k < NVARS; ++k) {
                u64 t[R_ROWS];
                #pragma unroll
                for (int r = 0; r < R_ROWS; ++r) t[r] = pack2(pij[r] * xb[r][k * CHUNK]);
                ACCR(t);
            }
        }
    }

    // Write 18 outputs per row as 9 float2 stores (rows are 72B strided).
    #pragma unroll
    for (int rr = 0; rr < R_ROWS; ++rr) {
        const int grow = base + tid + rr * BLOCK;
        if (grow < rows) {
            float* o = out + (size_t)grow * NVARS;
            #pragma unroll
            for (int n = 0; n < NACC; ++n) {
                float a, b;
                unpack2(acc[rr][n], a, b);
                ((float2*)o)[n] = make_float2(a, b);
            }
        }
    }
    #undef ACCR
}

extern "C" void kernel_launch(void* const* d_in, const int* in_sizes, int n_in,
                              void* d_out, int out_size)
{
    const float* z      = (const float*)d_in[0];
    const float* betas  = (const float*)d_in[1];
    const float* big_xi = (const float*)d_in[2];
    const float* mask   = (const float*)d_in[3];
    float* out = (float*)d_out;

    const int rows = in_sizes[0] / 16;   // z is [rows, 16]
    const int smem_bytes = (P_TOT * WPAD + NVARS * CHUNK) * (int)sizeof(float);

    cudaFuncSetAttribute(vindy_poly_kernel,
                         cudaFuncAttributeMaxDynamicSharedMemorySize, smem_bytes);

    const int grid = (rows + CHUNK - 1) / CHUNK;
    vindy_poly_kernel<<<grid, BLOCK, smem_bytes>>>(z, betas, big_xi, mask, out, rows);
}